// round 2
// baseline (speedup 1.0000x reference)
#include <cuda_runtime.h>
#include <math.h>

#define CH    96
#define HW    3136
#define DHW   25088
#define NTOK  50176
#define NSEQ  392
#define NELEM 4816896

__device__ float g_win [NTOK * 96];
__device__ float g_qkv0[NTOK * 288];
__device__ float g_qkv1[NTOK * 288];
__device__ float g_ao0 [NTOK * 96];
__device__ float g_ao1 [NTOK * 96];
__device__ float g_p0  [NTOK * 96];
__device__ float g_p1  [NTOK * 96];
__device__ float g_x1  [NELEM];
__device__ float g_x2  [NELEM];
__device__ float g_bias0[3 * 392 * 392];
__device__ float g_bias1[6 * 392 * 392];
__device__ float g_wt  [27 * 96 * 96];
__device__ unsigned char g_reg[64 * 392];
__device__ float g_aw[2];
__device__ float g_fw[4];

__global__ void k_setup1(const float* aa, const float* af) {
    if (threadIdx.x == 0) {
        float m = fmaxf(aa[0], aa[1]);
        float e0 = expf(aa[0] - m), e1 = expf(aa[1] - m);
        g_aw[0] = e0 / (e0 + e1); g_aw[1] = e1 / (e0 + e1);
        float mf = fmaxf(fmaxf(af[0], af[1]), fmaxf(af[2], af[3]));
        float e[4], s = 0.f;
        for (int i = 0; i < 4; i++) { e[i] = expf(af[i] - mf); s += e[i]; }
        for (int i = 0; i < 4; i++) g_fw[i] = e[i] / s;
    }
}

__global__ void k_setup2(const float* rpb0, const float* rpb1,
                         const float* c3w, const float* c1w) {
    int idx = blockIdx.x * 256 + threadIdx.x;
    if (idx < 64 * 392) {
        int widx = idx / 392, n = idx % 392;
        int di = n / 49, r = n % 49, hi = r / 7, wi = r % 7;
        int d = di, h = (widx >> 3) * 7 + hi, w = (widx & 7) * 7 + wi;
        int dc = (d < 4) ? 1 : 2;
        int hc = (h < 49) ? 0 : ((h < 53) ? 1 : 2);
        int wc = (w < 49) ? 0 : ((w < 53) ? 1 : 2);
        g_reg[idx] = (unsigned char)(dc * 9 + hc * 3 + wc);
    }
    if (idx < 392 * 392) {
        int i = idx / 392, j = idx % 392;
        int di = i / 49, ri = i % 49, hi = ri / 7, wi = ri % 7;
        int dj = j / 49, rj = j % 49, hj = rj / 7, wj = rj % 7;
        int rel = (di - dj + 7) * 169 + (hi - hj + 6) * 13 + (wi - wj + 6);
        for (int hh = 0; hh < 3; hh++) g_bias0[(hh * 392 + i) * 392 + j] = rpb0[rel * 3 + hh];
        for (int hh = 0; hh < 6; hh++) g_bias1[(hh * 392 + i) * 392 + j] = rpb1[rel * 6 + hh];
    }
    if (idx < 27 * 96 * 96) {
        int tap = idx / 9216, rem = idx % 9216;
        int co = rem / 96, ci = rem % 96;
        float v = g_fw[0] * c3w[(co * 96 + ci) * 27 + tap];
        if (tap == 13) v += g_fw[1] * c1w[co * 96 + ci];
        g_wt[idx] = v;
    }
}

// LayerNorm over C; mode 0: gather to shifted-window token layout, mode 1: plain.
__global__ void k_ln(const float* __restrict__ x, const float* __restrict__ gw,
                     const float* __restrict__ gb, float* __restrict__ out, int mode) {
    __shared__ float Xs[96 * 33];
    __shared__ float mu[32], rsg[32];
    int tid = threadIdx.x;
    int p0 = blockIdx.x * 32;
    for (int e = tid; e < 96 * 32; e += 256) {
        int c = e >> 5, pos = e & 31;
        int p = p0 + pos, b = p / DHW, rem = p % DHW;
        Xs[c * 33 + pos] = x[(b * 96 + c) * DHW + rem];
    }
    __syncthreads();
    if (tid < 32) {
        float s = 0.f, q = 0.f;
        for (int c = 0; c < 96; c++) { float v = Xs[c * 33 + tid]; s += v; q += v * v; }
        float m = s * (1.f / 96.f);
        mu[tid] = m;
        rsg[tid] = rsqrtf(q * (1.f / 96.f) - m * m + 1e-5f);
    }
    __syncthreads();
    if (mode == 0) {
        for (int e = tid; e < 32 * 96; e += 256) {
            int pos = e / 96, c = e % 96;
            int p = p0 + pos, b = p / DHW, rem = p % DHW;
            int d = rem / HW, r2 = rem % HW, h = r2 / 56, w = r2 % 56;
            float xn = (Xs[c * 33 + pos] - mu[pos]) * rsg[pos] * gw[c] + gb[c];
            int ds = (d + 4) & 7;
            int hs = (h >= 3) ? h - 3 : h + 53;
            int ws = (w >= 3) ? w - 3 : w + 53;
            int tok = (b * 64 + (hs / 7) * 8 + (ws / 7)) * NSEQ + ds * 49 + (hs % 7) * 7 + (ws % 7);
            out[tok * 96 + c] = xn;
        }
    } else {
        for (int e = tid; e < 96 * 32; e += 256) {
            int c = e >> 5, pos = e & 31;
            int p = p0 + pos, b = p / DHW, rem = p % DHW;
            float xn = (Xs[c * 33 + pos] - mu[pos]) * rsg[pos] * gw[c] + gb[c];
            out[(b * 96 + c) * DHW + rem] = xn;
        }
    }
}

// C[m][o] = sum_k A[m][k] * Wt[o][k] + bias[o]
__global__ void k_gemm(const float* __restrict__ A, const float* __restrict__ Wt,
                       const float* __restrict__ bias, float* __restrict__ Cc, int ldc) {
    __shared__ float As[64 * 33];
    __shared__ float Ws[96 * 33];
    int tid = threadIdx.x;
    int m0 = blockIdx.x * 64, o0 = blockIdx.y * 96;
    int tm = tid >> 4, to = tid & 15;
    float acc[4][6];
    #pragma unroll
    for (int i = 0; i < 4; i++)
        #pragma unroll
        for (int j = 0; j < 6; j++) acc[i][j] = 0.f;
    for (int ks = 0; ks < 96; ks += 32) {
        __syncthreads();
        for (int e = tid; e < 64 * 32; e += 256) {
            int m = e >> 5, k = e & 31;
            As[m * 33 + k] = A[(m0 + m) * 96 + ks + k];
        }
        for (int e = tid; e < 96 * 32; e += 256) {
            int o = e >> 5, k = e & 31;
            Ws[o * 33 + k] = Wt[(o0 + o) * 96 + ks + k];
        }
        __syncthreads();
        #pragma unroll
        for (int k = 0; k < 32; k++) {
            float a[4], wv[6];
            #pragma unroll
            for (int i = 0; i < 4; i++) a[i] = As[(tm * 4 + i) * 33 + k];
            #pragma unroll
            for (int j = 0; j < 6; j++) wv[j] = Ws[(to * 6 + j) * 33 + k];
            #pragma unroll
            for (int i = 0; i < 4; i++)
                #pragma unroll
                for (int j = 0; j < 6; j++) acc[i][j] += a[i] * wv[j];
        }
    }
    #pragma unroll
    for (int i = 0; i < 4; i++) {
        int m = m0 + tm * 4 + i;
        #pragma unroll
        for (int j = 0; j < 6; j++) {
            int o = o0 + to * 6 + j;
            Cc[(size_t)m * ldc + o] = acc[i][j] + bias[o];
        }
    }
}

// Flash-style window attention. grid (7 qblocks, 128 windows, h heads), block 256.
template <int DH>
__global__ void k_attn(const float* __restrict__ qkv, const float* __restrict__ bias,
                       float* __restrict__ ao) {
    constexpr int ND = DH + 1;
    constexpr int DPT = DH / 16;
    __shared__ float Qs[64 * ND];
    __shared__ float Ks[64 * ND];
    __shared__ float Vs[64 * ND];
    __shared__ float Ps[64 * 65];
    int tid = threadIdx.x;
    int ty = tid >> 4, tx = tid & 15;
    int n0 = blockIdx.x * 64;
    int bw = blockIdx.y;
    int head = blockIdx.z;
    int widx = bw & 63;
    float scale = rsqrtf((float)DH);

    for (int e = tid; e < 64 * DH; e += 256) {
        int r = e / DH, k = e % DH;
        int n = n0 + r;
        Qs[r * ND + k] = (n < NSEQ) ? qkv[(bw * NSEQ + n) * 288 + head * DH + k] * scale : 0.f;
    }

    float mi[4], li[4], oacc[4][DPT];
    unsigned char regn[4];
    #pragma unroll
    for (int i = 0; i < 4; i++) {
        mi[i] = -INFINITY; li[i] = 0.f;
        #pragma unroll
        for (int d2 = 0; d2 < DPT; d2++) oacc[i][d2] = 0.f;
        int n = n0 + ty * 4 + i; if (n > 391) n = 391;
        regn[i] = g_reg[widx * 392 + n];
    }

    for (int m0 = 0; m0 < NSEQ; m0 += 64) {
        __syncthreads();
        for (int e = tid; e < 64 * DH; e += 256) {
            int r = e / DH, k = e % DH;
            int m = m0 + r;
            if (m < NSEQ) {
                int base = (bw * NSEQ + m) * 288 + head * DH + k;
                Ks[r * ND + k] = qkv[base + 96];
                Vs[r * ND + k] = qkv[base + 192];
            } else { Ks[r * ND + k] = 0.f; Vs[r * ND + k] = 0.f; }
        }
        __syncthreads();
        float s[4][4];
        #pragma unroll
        for (int i = 0; i < 4; i++)
            #pragma unroll
            for (int j = 0; j < 4; j++) s[i][j] = 0.f;
        #pragma unroll
        for (int k = 0; k < DH; k++) {
            float a[4], b2[4];
            #pragma unroll
            for (int i = 0; i < 4; i++) a[i] = Qs[(ty * 4 + i) * ND + k];
            #pragma unroll
            for (int j = 0; j < 4; j++) b2[j] = Ks[(tx * 4 + j) * ND + k];
            #pragma unroll
            for (int i = 0; i < 4; i++)
                #pragma unroll
                for (int j = 0; j < 4; j++) s[i][j] += a[i] * b2[j];
        }
        #pragma unroll
        for (int i = 0; i < 4; i++) {
            int n = n0 + ty * 4 + i; if (n > 391) n = 391;
            #pragma unroll
            for (int j = 0; j < 4; j++) {
                int m = m0 + tx * 4 + j;
                if (m < NSEQ) {
                    s[i][j] += bias[((size_t)head * 392 + n) * 392 + m];
                    if (g_reg[widx * 392 + m] != regn[i]) s[i][j] -= 100.f;
                } else s[i][j] = -1e30f;
            }
        }
        #pragma unroll
        for (int i = 0; i < 4; i++) {
            float rm = fmaxf(fmaxf(s[i][0], s[i][1]), fmaxf(s[i][2], s[i][3]));
            #pragma unroll
            for (int o = 1; o < 16; o <<= 1) rm = fmaxf(rm, __shfl_xor_sync(0xffffffffu, rm, o));
            float mnew = fmaxf(mi[i], rm);
            float f = __expf(mi[i] - mnew);
            float rs2 = 0.f;
            #pragma unroll
            for (int j = 0; j < 4; j++) { float p = __expf(s[i][j] - mnew); s[i][j] = p; rs2 += p; }
            #pragma unroll
            for (int o = 1; o < 16; o <<= 1) rs2 += __shfl_xor_sync(0xffffffffu, rs2, o);
            li[i] = li[i] * f + rs2;
            mi[i] = mnew;
            #pragma unroll
            for (int d2 = 0; d2 < DPT; d2++) oacc[i][d2] *= f;
        }
        #pragma unroll
        for (int i = 0; i < 4; i++)
            #pragma unroll
            for (int j = 0; j < 4; j++) Ps[(ty * 4 + i) * 65 + tx * 4 + j] = s[i][j];
        __syncthreads();
        #pragma unroll 4
        for (int m = 0; m < 64; m++) {
            float pv[4], vv[DPT];
            #pragma unroll
            for (int i = 0; i < 4; i++) pv[i] = Ps[(ty * 4 + i) * 65 + m];
            #pragma unroll
            for (int d2 = 0; d2 < DPT; d2++) vv[d2] = Vs[m * ND + tx * DPT + d2];
            #pragma unroll
            for (int i = 0; i < 4; i++)
                #pragma unroll
                for (int d2 = 0; d2 < DPT; d2++) oacc[i][d2] += pv[i] * vv[d2];
        }
    }
    #pragma unroll
    for (int i = 0; i < 4; i++) {
        int n = n0 + ty * 4 + i;
        if (n < NSEQ) {
            float inv = 1.f / li[i];
            #pragma unroll
            for (int d2 = 0; d2 < DPT; d2++)
                ao[(bw * NSEQ + n) * 96 + head * DH + tx * DPT + d2] = oacc[i][d2] * inv;
        }
    }
}

// mix projections + window reverse + unshift + residual
__global__ void k_combine(const float* __restrict__ x, float* __restrict__ x1out) {
    __shared__ float S[96 * 33];
    __shared__ int ts[32];
    int tid = threadIdx.x;
    int p0 = blockIdx.x * 32;
    if (tid < 32) {
        int p = p0 + tid, b = p / DHW, rem = p % DHW;
        int d = rem / HW, r2 = rem % HW, h = r2 / 56, w = r2 % 56;
        int dr = (d + 4) & 7, hr = (h + 53) % 56, wr = (w + 53) % 56;
        ts[tid] = (b * 64 + (hr / 7) * 8 + wr / 7) * NSEQ + dr * 49 + (hr % 7) * 7 + (wr % 7);
    }
    __syncthreads();
    float a0 = g_aw[0], a1 = g_aw[1];
    for (int e = tid; e < 32 * 96; e += 256) {
        int pos = e / 96, c = e % 96;
        int t = ts[pos];
        S[c * 33 + pos] = a0 * g_p0[t * 96 + c] + a1 * g_p1[t * 96 + c];
    }
    __syncthreads();
    for (int e = tid; e < 96 * 32; e += 256) {
        int c = e >> 5, pos = e & 31;
        int p = p0 + pos, b = p / DHW, rem = p % DHW;
        int oi = (b * 96 + c) * DHW + rem;
        x1out[oi] = x[oi] + S[c * 33 + pos];
    }
}

// FFN: merged conv3/conv1 tap-GEMMs + dwconv + identity + residual.
__global__ void k_ffn(const float* __restrict__ c3b, const float* __restrict__ c1b,
                      const float* __restrict__ dww, const float* __restrict__ dwb,
                      float* __restrict__ out) {
    __shared__ float Ws[96 * 49];
    __shared__ float Xs[48 * 60];
    int tid = threadIdx.x;
    int rb = blockIdx.x;
    int b = rb / 448, r = rb % 448;
    int d = r / 56, h = r % 56;
    int tw = tid >> 4, tco = tid & 15;
    int co0 = tco * 6, w0 = tw * 4;
    float acc[6][4], dwacc[6][4];
    #pragma unroll
    for (int i = 0; i < 6; i++)
        #pragma unroll
        for (int j = 0; j < 4; j++) { acc[i][j] = 0.f; dwacc[i][j] = 0.f; }

    for (int kd = 0; kd < 3; kd++) {
        int d2 = d + kd - 1;
        bool dok = (d2 >= 0) && (d2 < 8);
        for (int kh = 0; kh < 3; kh++) {
            int h2 = h + kh - 1;
            bool hok = dok && (h2 >= 0) && (h2 < 56);
            for (int half = 0; half < 2; half++) {
                int ci0 = half * 48;
                __syncthreads();
                for (int e = tid; e < 48 * 58; e += 224) {
                    int ci = e / 58, t2 = e % 58;
                    int w2 = t2 - 1;
                    float v = 0.f;
                    if (hok && w2 >= 0 && w2 < 56)
                        v = g_x2[((b * 96 + ci0 + ci) * 8 + d2) * HW + h2 * 56 + w2];
                    Xs[ci * 60 + t2] = v;
                }
                bool my_half = ((tco >= 8) ? 1 : 0) == half;
                for (int kw = 0; kw < 3; kw++) {
                    int tap = (kd * 3 + kh) * 3 + kw;
                    if (kw > 0) __syncthreads();
                    for (int e = tid; e < 96 * 48; e += 224) {
                        int co = e / 48, cl = e % 48;
                        Ws[co * 49 + cl] = g_wt[tap * 9216 + co * 96 + ci0 + cl];
                    }
                    __syncthreads();
                    #pragma unroll 4
                    for (int cl = 0; cl < 48; cl++) {
                        float a[6], xv[4];
                        #pragma unroll
                        for (int i = 0; i < 6; i++) a[i] = Ws[(co0 + i) * 49 + cl];
                        #pragma unroll
                        for (int j = 0; j < 4; j++) xv[j] = Xs[cl * 60 + w0 + j + kw];
                        #pragma unroll
                        for (int i = 0; i < 6; i++)
                            #pragma unroll
                            for (int j = 0; j < 4; j++) acc[i][j] += a[i] * xv[j];
                    }
                    if (my_half) {
                        #pragma unroll
                        for (int i = 0; i < 6; i++) {
                            int co = co0 + i;
                            float wdw = dww[co * 27 + tap];
                            int col = co - ci0;
                            #pragma unroll
                            for (int j = 0; j < 4; j++)
                                dwacc[i][j] += wdw * Xs[col * 60 + w0 + j + kw];
                        }
                    }
                }
            }
        }
    }
    float fw0 = g_fw[0], fw1 = g_fw[1], fw2 = g_fw[2], fw3 = g_fw[3];
    (void)fw0; (void)fw1;
    #pragma unroll
    for (int i = 0; i < 6; i++) {
        int co = co0 + i;
        float cb = g_fw[0] * c3b[co] + g_fw[1] * c1b[co] + fw2 * dwb[co];
        #pragma unroll
        for (int j = 0; j < 4; j++) {
            int w = w0 + j;
            int oi = ((b * 96 + co) * 8 + d) * HW + h * 56 + w;
            float x2v = g_x2[oi];
            out[oi] = g_x1[oi] + acc[i][j] + fw2 * dwacc[i][j] + fw3 * x2v + cb;
        }
    }
}

extern "C" void kernel_launch(void* const* d_in, const int* in_sizes, int n_in,
                              void* d_out, int out_size) {
    const float* x       = (const float*)d_in[0];
    const float* ln1_w   = (const float*)d_in[1];
    const float* ln1_b   = (const float*)d_in[2];
    const float* ln2_w   = (const float*)d_in[3];
    const float* ln2_b   = (const float*)d_in[4];
    const float* qkv_w0  = (const float*)d_in[5];
    const float* qkv_b0  = (const float*)d_in[6];
    const float* proj_w0 = (const float*)d_in[7];
    const float* proj_b0 = (const float*)d_in[8];
    const float* rpb0    = (const float*)d_in[9];
    const float* qkv_w1  = (const float*)d_in[10];
    const float* qkv_b1  = (const float*)d_in[11];
    const float* proj_w1 = (const float*)d_in[12];
    const float* proj_b1 = (const float*)d_in[13];
    const float* rpb1    = (const float*)d_in[14];
    const float* a_attn  = (const float*)d_in[15];
    const float* conv3_w = (const float*)d_in[16];
    const float* conv3_b = (const float*)d_in[17];
    const float* conv1_w = (const float*)d_in[18];
    const float* conv1_b = (const float*)d_in[19];
    const float* dw_w    = (const float*)d_in[20];
    const float* dw_b    = (const float*)d_in[21];
    const float* a_ffn   = (const float*)d_in[22];
    float* out = (float*)d_out;

    float *p_win, *p_qkv0, *p_qkv1, *p_ao0, *p_ao1, *p_p0, *p_p1, *p_x1, *p_x2, *p_b0, *p_b1;
    cudaGetSymbolAddress((void**)&p_win,  g_win);
    cudaGetSymbolAddress((void**)&p_qkv0, g_qkv0);
    cudaGetSymbolAddress((void**)&p_qkv1, g_qkv1);
    cudaGetSymbolAddress((void**)&p_ao0,  g_ao0);
    cudaGetSymbolAddress((void**)&p_ao1,  g_ao1);
    cudaGetSymbolAddress((void**)&p_p0,   g_p0);
    cudaGetSymbolAddress((void**)&p_p1,   g_p1);
    cudaGetSymbolAddress((void**)&p_x1,   g_x1);
    cudaGetSymbolAddress((void**)&p_x2,   g_x2);
    cudaGetSymbolAddress((void**)&p_b0,   g_bias0);
    cudaGetSymbolAddress((void**)&p_b1,   g_bias1);

    k_setup1<<<1, 32>>>(a_attn, a_ffn);
    k_setup2<<<972, 256>>>(rpb0, rpb1, conv3_w, conv1_w);

    k_ln<<<1568, 256>>>(x, ln1_w, ln1_b, p_win, 0);

    k_gemm<<<dim3(784, 3), 256>>>(p_win, qkv_w0, qkv_b0, p_qkv0, 288);
    k_gemm<<<dim3(784, 3), 256>>>(p_win, qkv_w1, qkv_b1, p_qkv1, 288);

    k_attn<32><<<dim3(7, 128, 3), 256>>>(p_qkv0, p_b0, p_ao0);
    k_attn<16><<<dim3(7, 128, 6), 256>>>(p_qkv1, p_b1, p_ao1);

    k_gemm<<<dim3(784, 1), 256>>>(p_ao0, proj_w0, proj_b0, p_p0, 96);
    k_gemm<<<dim3(784, 1), 256>>>(p_ao1, proj_w1, proj_b1, p_p1, 96);

    k_combine<<<1568, 256>>>(x, p_x1);
    k_ln<<<1568, 256>>>(p_x1, ln2_w, ln2_b, p_x2, 1);

    k_ffn<<<896, 224>>>(conv3_b, conv1_b, dw_w, dw_b, out);
}

// round 3
// speedup vs baseline: 1.0531x; 1.0531x over previous
#include <cuda_runtime.h>
#include <math.h>

#define CH    96
#define HW    3136
#define DHW   25088
#define NTOK  50176
#define NSEQ  392
#define NELEM 4816896

__device__ float g_win [NTOK * 96];
__device__ float g_qkv0[NTOK * 288];
__device__ float g_qkv1[NTOK * 288];
__device__ float g_ao0 [NTOK * 96];
__device__ float g_ao1 [NTOK * 96];
__device__ float g_p0  [NTOK * 96];
__device__ float g_p1  [NTOK * 96];
__device__ float g_x1  [NELEM];
__device__ float g_x2  [NELEM];
__device__ float g_cb0 [4 * 3 * 392 * 392];   // bias+mask fused, attn0
__device__ float g_cb1 [4 * 6 * 392 * 392];   // bias+mask fused, attn1
__device__ float g_wt  [27 * 96 * 96];        // merged conv3 + conv1 + dw + identity
__device__ float g_cbv [96];                  // merged conv bias
__device__ float g_aw[2];
__device__ float g_fw[4];

__global__ void k_setup1(const float* aa, const float* af) {
    if (threadIdx.x == 0) {
        float m = fmaxf(aa[0], aa[1]);
        float e0 = expf(aa[0] - m), e1 = expf(aa[1] - m);
        g_aw[0] = e0 / (e0 + e1); g_aw[1] = e1 / (e0 + e1);
        float mf = fmaxf(fmaxf(af[0], af[1]), fmaxf(af[2], af[3]));
        float e[4], s = 0.f;
        for (int i = 0; i < 4; i++) { e[i] = expf(af[i] - mf); s += e[i]; }
        for (int i = 0; i < 4; i++) g_fw[i] = e[i] / s;
    }
}

__global__ void k_setup2(const float* rpb0, const float* rpb1,
                         const float* c3w, const float* c1w, const float* dww,
                         const float* c3b, const float* c1b, const float* dwb) {
    int idx = blockIdx.x * 256 + threadIdx.x;
    if (idx < 4 * 392 * 392) {
        int type = idx / 153664, rem = idx % 153664;
        int i = rem / 392, j = rem % 392;
        int di = i / 49, ri = i % 49, hi = ri / 7, wi = ri % 7;
        int dj = j / 49, rj = j % 49, hj = rj / 7, wj = rj % 7;
        int rel = (di - dj + 7) * 169 + (hi - hj + 6) * 13 + (wi - wj + 6);
        int dcA = (di < 4) ? 0 : 1, dcB = (dj < 4) ? 0 : 1;
        int hcA = (type & 2) ? ((hi < 4) ? 1 : 2) : 0;
        int hcB = (type & 2) ? ((hj < 4) ? 1 : 2) : 0;
        int wcA = (type & 1) ? ((wi < 4) ? 1 : 2) : 0;
        int wcB = (type & 1) ? ((wj < 4) ? 1 : 2) : 0;
        float mv = (dcA != dcB || hcA != hcB || wcA != wcB) ? -100.f : 0.f;
        for (int hh = 0; hh < 3; hh++)
            g_cb0[((type * 3 + hh) * 392 + i) * 392 + j] = rpb0[rel * 3 + hh] + mv;
        for (int hh = 0; hh < 6; hh++)
            g_cb1[((type * 6 + hh) * 392 + i) * 392 + j] = rpb1[rel * 6 + hh] + mv;
    }
    if (idx < 27 * 96 * 96) {
        int tap = idx / 9216, rem2 = idx % 9216;
        int co = rem2 / 96, ci = rem2 % 96;
        float v = g_fw[0] * c3w[(co * 96 + ci) * 27 + tap];
        if (tap == 13) {
            v += g_fw[1] * c1w[co * 96 + ci];
            if (ci == co) v += g_fw[3];
        }
        if (ci == co) v += g_fw[2] * dww[co * 27 + tap];
        g_wt[idx] = v;
    }
    if (idx < 96) g_cbv[idx] = g_fw[0] * c3b[idx] + g_fw[1] * c1b[idx] + g_fw[2] * dwb[idx];
}

// LN over C + shift + window-partition gather
__global__ void k_ln(const float* __restrict__ x, const float* __restrict__ gw,
                     const float* __restrict__ gb, float* __restrict__ out) {
    __shared__ float Xs[96 * 33];
    __shared__ float mu[32], rsg[32];
    int tid = threadIdx.x;
    int p0 = blockIdx.x * 32;
    for (int e = tid; e < 96 * 32; e += 256) {
        int c = e >> 5, pos = e & 31;
        int p = p0 + pos, b = p / DHW, rem = p % DHW;
        Xs[c * 33 + pos] = x[(b * 96 + c) * DHW + rem];
    }
    __syncthreads();
    if (tid < 32) {
        float s = 0.f, q = 0.f;
        for (int c = 0; c < 96; c++) { float v = Xs[c * 33 + tid]; s += v; q += v * v; }
        float m = s * (1.f / 96.f);
        mu[tid] = m;
        rsg[tid] = rsqrtf(q * (1.f / 96.f) - m * m + 1e-5f);
    }
    __syncthreads();
    for (int e = tid; e < 32 * 96; e += 256) {
        int pos = e / 96, c = e % 96;
        int p = p0 + pos, b = p / DHW, rem = p % DHW;
        int d = rem / HW, r2 = rem % HW, h = r2 / 56, w = r2 % 56;
        float xn = (Xs[c * 33 + pos] - mu[pos]) * rsg[pos] * gw[c] + gb[c];
        int ds = (d + 4) & 7;
        int hs = (h >= 3) ? h - 3 : h + 53;
        int ws = (w >= 3) ? w - 3 : w + 53;
        int tok = (b * 64 + (hs / 7) * 8 + (ws / 7)) * NSEQ + ds * 49 + (hs % 7) * 7 + (ws % 7);
        out[tok * 96 + c] = xn;
    }
}

// C[m][o] = sum_k A[m][k]*Wt[o][k] + bias[o]; tile 128x96, microtile 8x6
__global__ void k_gemm(const float* __restrict__ A, const float* __restrict__ Wt,
                       const float* __restrict__ bias, float* __restrict__ Cc, int ldc) {
    __shared__ float As[128 * 33];
    __shared__ float Ws[96 * 33];
    int tid = threadIdx.x;
    int m0 = blockIdx.x * 128, o0 = blockIdx.y * 96;
    int tm = tid >> 4, to = tid & 15;
    float acc[8][6];
    #pragma unroll
    for (int i = 0; i < 8; i++)
        #pragma unroll
        for (int j = 0; j < 6; j++) acc[i][j] = 0.f;
    for (int ks = 0; ks < 96; ks += 32) {
        __syncthreads();
        for (int e = tid; e < 128 * 32; e += 256) {
            int m = e >> 5, k = e & 31;
            As[m * 33 + k] = A[(m0 + m) * 96 + ks + k];
        }
        for (int e = tid; e < 96 * 32; e += 256) {
            int o = e >> 5, k = e & 31;
            Ws[o * 33 + k] = Wt[(o0 + o) * 96 + ks + k];
        }
        __syncthreads();
        #pragma unroll
        for (int k = 0; k < 32; k++) {
            float a[8], wv[6];
            #pragma unroll
            for (int i = 0; i < 8; i++) a[i] = As[(tm * 8 + i) * 33 + k];
            #pragma unroll
            for (int j = 0; j < 6; j++) wv[j] = Ws[(to * 6 + j) * 33 + k];
            #pragma unroll
            for (int i = 0; i < 8; i++)
                #pragma unroll
                for (int j = 0; j < 6; j++) acc[i][j] += a[i] * wv[j];
        }
    }
    #pragma unroll
    for (int i = 0; i < 8; i++) {
        int m = m0 + tm * 8 + i;
        #pragma unroll
        for (int j = 0; j < 6; j++) {
            int o = o0 + to * 6 + j;
            Cc[m * ldc + o] = acc[i][j] + bias[o];
        }
    }
}

// Flash-style window attention with fused bias+mask table.
template <int DH, int H>
__global__ void k_attn(const float* __restrict__ qkv, const float* __restrict__ bias,
                       float* __restrict__ ao) {
    constexpr int ND = DH + 1;
    constexpr int DPT = DH / 16;
    __shared__ float Qs[64 * ND];
    __shared__ float Ks[64 * ND];
    __shared__ float Vs[64 * ND];
    __shared__ float Ps[64 * 65];
    int tid = threadIdx.x;
    int ty = tid >> 4, tx = tid & 15;
    int n0 = blockIdx.x * 64;
    int bw = blockIdx.y;
    int head = blockIdx.z;
    int widx = bw & 63;
    int type = (((widx >> 3) == 7) ? 2 : 0) + (((widx & 7) == 7) ? 1 : 0);
    float scale = rsqrtf((float)DH);

    for (int e = tid; e < 64 * DH; e += 256) {
        int r = e / DH, k = e % DH;
        int n = n0 + r;
        Qs[r * ND + k] = (n < NSEQ) ? qkv[(bw * NSEQ + n) * 288 + head * DH + k] * scale : 0.f;
    }

    float mi[4], li[4], oacc[4][DPT];
    const float* brow[4];
    #pragma unroll
    for (int i = 0; i < 4; i++) {
        mi[i] = -INFINITY; li[i] = 0.f;
        #pragma unroll
        for (int d2 = 0; d2 < DPT; d2++) oacc[i][d2] = 0.f;
        int n = n0 + ty * 4 + i; if (n > 391) n = 391;
        brow[i] = bias + ((type * H + head) * 392 + n) * 392;
    }

    for (int m0 = 0; m0 < NSEQ; m0 += 64) {
        __syncthreads();
        for (int e = tid; e < 64 * DH; e += 256) {
            int r = e / DH, k = e % DH;
            int m = m0 + r;
            if (m < NSEQ) {
                int base = (bw * NSEQ + m) * 288 + head * DH + k;
                Ks[r * ND + k] = qkv[base + 96];
                Vs[r * ND + k] = qkv[base + 192];
            } else { Ks[r * ND + k] = 0.f; Vs[r * ND + k] = 0.f; }
        }
        __syncthreads();
        float s[4][4];
        #pragma unroll
        for (int i = 0; i < 4; i++)
            #pragma unroll
            for (int j = 0; j < 4; j++) s[i][j] = 0.f;
        #pragma unroll
        for (int k = 0; k < DH; k++) {
            float a[4], b2[4];
            #pragma unroll
            for (int i = 0; i < 4; i++) a[i] = Qs[(ty * 4 + i) * ND + k];
            #pragma unroll
            for (int j = 0; j < 4; j++) b2[j] = Ks[(tx * 4 + j) * ND + k];
            #pragma unroll
            for (int i = 0; i < 4; i++)
                #pragma unroll
                for (int j = 0; j < 4; j++) s[i][j] += a[i] * b2[j];
        }
        int mb = m0 + tx * 4;
        #pragma unroll
        for (int i = 0; i < 4; i++) {
            #pragma unroll
            for (int j = 0; j < 4; j++) {
                int m = mb + j;
                if (m < 392) s[i][j] += __ldg(brow[i] + m);
                else s[i][j] = -1e30f;
            }
        }
        #pragma unroll
        for (int i = 0; i < 4; i++) {
            float rm = fmaxf(fmaxf(s[i][0], s[i][1]), fmaxf(s[i][2], s[i][3]));
            #pragma unroll
            for (int o = 1; o < 16; o <<= 1) rm = fmaxf(rm, __shfl_xor_sync(0xffffffffu, rm, o));
            float mnew = fmaxf(mi[i], rm);
            float f = __expf(mi[i] - mnew);
            float rs2 = 0.f;
            #pragma unroll
            for (int j = 0; j < 4; j++) { float p = __expf(s[i][j] - mnew); s[i][j] = p; rs2 += p; }
            #pragma unroll
            for (int o = 1; o < 16; o <<= 1) rs2 += __shfl_xor_sync(0xffffffffu, rs2, o);
            li[i] = li[i] * f + rs2;
            mi[i] = mnew;
            #pragma unroll
            for (int d2 = 0; d2 < DPT; d2++) oacc[i][d2] *= f;
        }
        #pragma unroll
        for (int i = 0; i < 4; i++)
            #pragma unroll
            for (int j = 0; j < 4; j++) Ps[(ty * 4 + i) * 65 + tx * 4 + j] = s[i][j];
        __syncthreads();
        #pragma unroll 4
        for (int m = 0; m < 64; m++) {
            float pv[4], vv[DPT];
            #pragma unroll
            for (int i = 0; i < 4; i++) pv[i] = Ps[(ty * 4 + i) * 65 + m];
            #pragma unroll
            for (int d2 = 0; d2 < DPT; d2++) vv[d2] = Vs[m * ND + tx * DPT + d2];
            #pragma unroll
            for (int i = 0; i < 4; i++)
                #pragma unroll
                for (int d2 = 0; d2 < DPT; d2++) oacc[i][d2] += pv[i] * vv[d2];
        }
    }
    #pragma unroll
    for (int i = 0; i < 4; i++) {
        int n = n0 + ty * 4 + i;
        if (n < NSEQ) {
            float inv = 1.f / li[i];
            #pragma unroll
            for (int d2 = 0; d2 < DPT; d2++)
                ao[(bw * NSEQ + n) * 96 + head * DH + tx * DPT + d2] = oacc[i][d2] * inv;
        }
    }
}

// mix projections + window reverse + unshift + residual + LN2 (fused)
__global__ void k_comb_ln(const float* __restrict__ x, const float* __restrict__ w2,
                          const float* __restrict__ b2) {
    __shared__ float S[96 * 33];
    __shared__ int ts[32];
    __shared__ float mu[32], rsg[32];
    int tid = threadIdx.x;
    int p0 = blockIdx.x * 32;
    if (tid < 32) {
        int p = p0 + tid, b = p / DHW, rem = p % DHW;
        int d = rem / HW, r2 = rem % HW, h = r2 / 56, w = r2 % 56;
        int dr = (d + 4) & 7, hr = (h + 53) % 56, wr = (w + 53) % 56;
        ts[tid] = (b * 64 + (hr / 7) * 8 + wr / 7) * NSEQ + dr * 49 + (hr % 7) * 7 + (wr % 7);
    }
    __syncthreads();
    float a0 = g_aw[0], a1 = g_aw[1];
    for (int e = tid; e < 32 * 96; e += 256) {
        int pos = e / 96, c = e % 96;
        int t = ts[pos];
        S[c * 33 + pos] = a0 * g_p0[t * 96 + c] + a1 * g_p1[t * 96 + c];
    }
    __syncthreads();
    for (int e = tid; e < 96 * 32; e += 256) {
        int c = e >> 5, pos = e & 31;
        int p = p0 + pos, b = p / DHW, rem = p % DHW;
        int oi = (b * 96 + c) * DHW + rem;
        float v = x[oi] + S[c * 33 + pos];
        S[c * 33 + pos] = v;
        g_x1[oi] = v;
    }
    __syncthreads();
    if (tid < 32) {
        float s = 0.f, q = 0.f;
        for (int c = 0; c < 96; c++) { float v = S[c * 33 + tid]; s += v; q += v * v; }
        float m = s * (1.f / 96.f);
        mu[tid] = m;
        rsg[tid] = rsqrtf(q * (1.f / 96.f) - m * m + 1e-5f);
    }
    __syncthreads();
    for (int e = tid; e < 96 * 32; e += 256) {
        int c = e >> 5, pos = e & 31;
        int p = p0 + pos, b = p / DHW, rem = p % DHW;
        float xn = (S[c * 33 + pos] - mu[pos]) * rsg[pos] * w2[c] + b2[c];
        g_x2[(b * 96 + c) * DHW + rem] = xn;
    }
}

// FFN: pure 27-tap implicit GEMM (dw + identity folded into g_wt diagonal).
// Block: 96co x 112 (two h-rows), 256 threads, microtile 6x7.
__global__ void k_ffn(float* __restrict__ out) {
    __shared__ float Xs[24 * 240];   // 24 ci x 4 h-rows x 60
    __shared__ float Ws[96 * 25];
    int tid = threadIdx.x;
    int bx = blockIdx.x;
    int b = bx / 224, r = bx % 224;
    int d = r / 28, h0 = (r % 28) * 2;
    int tco = tid >> 4, tcol = tid & 15;
    int co0 = tco * 6;
    int coff[7], rj[7], wj[7];
    #pragma unroll
    for (int j = 0; j < 7; j++) {
        int col = tcol * 7 + j;
        rj[j] = (col >= 56) ? 1 : 0;
        wj[j] = col - 56 * rj[j];
        coff[j] = rj[j] * 60 + wj[j];
    }
    float acc[6][7];
    #pragma unroll
    for (int i = 0; i < 6; i++)
        #pragma unroll
        for (int j = 0; j < 7; j++) acc[i][j] = 0.f;

    for (int kd = 0; kd < 3; kd++) {
        int d2 = d + kd - 1;
        bool dok = (d2 >= 0) && (d2 < 8);
        for (int q = 0; q < 4; q++) {
            __syncthreads();
            for (int e = tid; e < 24 * 4 * 58; e += 256) {
                int ci = e / 232, rem2 = e % 232;
                int lr = rem2 / 58, t = rem2 % 58;
                int h2 = h0 - 1 + lr, w2 = t - 1;
                float v = 0.f;
                if (dok && h2 >= 0 && h2 < 56 && w2 >= 0 && w2 < 56)
                    v = g_x2[((b * 96 + q * 24 + ci) * 8 + d2) * HW + h2 * 56 + w2];
                Xs[ci * 240 + lr * 60 + t] = v;
            }
            for (int kh = 0; kh < 3; kh++) {
                for (int kw = 0; kw < 3; kw++) {
                    int tap = (kd * 3 + kh) * 3 + kw;
                    __syncthreads();
                    for (int e = tid; e < 96 * 24; e += 256) {
                        int co = e / 24, kk = e % 24;
                        Ws[co * 25 + kk] = g_wt[tap * 9216 + co * 96 + q * 24 + kk];
                    }
                    __syncthreads();
                    int kbase = kh * 60 + kw;
                    #pragma unroll 4
                    for (int k = 0; k < 24; k++) {
                        float a[6], xv[7];
                        #pragma unroll
                        for (int i = 0; i < 6; i++) a[i] = Ws[(co0 + i) * 25 + k];
                        #pragma unroll
                        for (int j = 0; j < 7; j++) xv[j] = Xs[k * 240 + coff[j] + kbase];
                        #pragma unroll
                        for (int i = 0; i < 6; i++)
                            #pragma unroll
                            for (int j = 0; j < 7; j++) acc[i][j] += a[i] * xv[j];
                    }
                }
            }
        }
    }
    #pragma unroll
    for (int i = 0; i < 6; i++) {
        int co = co0 + i;
        float cb = g_cbv[co];
        #pragma unroll
        for (int j = 0; j < 7; j++) {
            int oi = ((b * 96 + co) * 8 + d) * HW + (h0 + rj[j]) * 56 + wj[j];
            out[oi] = g_x1[oi] + acc[i][j] + cb;
        }
    }
}

extern "C" void kernel_launch(void* const* d_in, const int* in_sizes, int n_in,
                              void* d_out, int out_size) {
    const float* x       = (const float*)d_in[0];
    const float* ln1_w   = (const float*)d_in[1];
    const float* ln1_b   = (const float*)d_in[2];
    const float* ln2_w   = (const float*)d_in[3];
    const float* ln2_b   = (const float*)d_in[4];
    const float* qkv_w0  = (const float*)d_in[5];
    const float* qkv_b0  = (const float*)d_in[6];
    const float* proj_w0 = (const float*)d_in[7];
    const float* proj_b0 = (const float*)d_in[8];
    const float* rpb0    = (const float*)d_in[9];
    const float* qkv_w1  = (const float*)d_in[10];
    const float* qkv_b1  = (const float*)d_in[11];
    const float* proj_w1 = (const float*)d_in[12];
    const float* proj_b1 = (const float*)d_in[13];
    const float* rpb1    = (const float*)d_in[14];
    const float* a_attn  = (const float*)d_in[15];
    const float* conv3_w = (const float*)d_in[16];
    const float* conv3_b = (const float*)d_in[17];
    const float* conv1_w = (const float*)d_in[18];
    const float* conv1_b = (const float*)d_in[19];
    const float* dw_w    = (const float*)d_in[20];
    const float* dw_b    = (const float*)d_in[21];
    const float* a_ffn   = (const float*)d_in[22];
    float* out = (float*)d_out;

    float *p_win, *p_qkv0, *p_qkv1, *p_ao0, *p_ao1, *p_p0, *p_p1, *p_cb0, *p_cb1;
    cudaGetSymbolAddress((void**)&p_win,  g_win);
    cudaGetSymbolAddress((void**)&p_qkv0, g_qkv0);
    cudaGetSymbolAddress((void**)&p_qkv1, g_qkv1);
    cudaGetSymbolAddress((void**)&p_ao0,  g_ao0);
    cudaGetSymbolAddress((void**)&p_ao1,  g_ao1);
    cudaGetSymbolAddress((void**)&p_p0,   g_p0);
    cudaGetSymbolAddress((void**)&p_p1,   g_p1);
    cudaGetSymbolAddress((void**)&p_cb0,  g_cb0);
    cudaGetSymbolAddress((void**)&p_cb1,  g_cb1);

    k_setup1<<<1, 32>>>(a_attn, a_ffn);
    k_setup2<<<2401, 256>>>(rpb0, rpb1, conv3_w, conv1_w, dw_w, conv3_b, conv1_b, dw_b);

    k_ln<<<1568, 256>>>(x, ln1_w, ln1_b, p_win);

    k_gemm<<<dim3(392, 3), 256>>>(p_win, qkv_w0, qkv_b0, p_qkv0, 288);
    k_gemm<<<dim3(392, 3), 256>>>(p_win, qkv_w1, qkv_b1, p_qkv1, 288);

    k_attn<32, 3><<<dim3(7, 128, 3), 256>>>(p_qkv0, p_cb0, p_ao0);
    k_attn<16, 6><<<dim3(7, 128, 6), 256>>>(p_qkv1, p_cb1, p_ao1);

    k_gemm<<<dim3(392, 1), 256>>>(p_ao0, proj_w0, proj_b0, p_p0, 96);
    k_gemm<<<dim3(392, 1), 256>>>(p_ao1, proj_w1, proj_b1, p_p1, 96);

    k_comb_ln<<<1568, 256>>>(x, ln2_w, ln2_b);

    k_ffn<<<448, 256>>>(out);
}